// round 6
// baseline (speedup 1.0000x reference)
#include <cuda_runtime.h>
#include <cuda_bf16.h>
#include <cstdint>

#define BATCH 512
#define SEQ   256
#define EMBED 384
#define HDIM  64
#define NROWS (BATCH * SEQ)   // 131072

typedef uint16_t half_t;

// ---------------------------------------------------------------------------
// Global scratch: projected Q/K/V in split bf16.
//   Qh/Ql, Kh/Kl: [b][s][d]   (row.col mma layout for S = Q K^T)
//   Vth/Vtl:      [b][d][s]   (B operand layout for O = P V)
// W split-bf16: [mat][n][k].
// ---------------------------------------------------------------------------
__device__ half_t g_Qh[(size_t)NROWS * HDIM];
__device__ half_t g_Ql[(size_t)NROWS * HDIM];
__device__ half_t g_Kh[(size_t)NROWS * HDIM];
__device__ half_t g_Kl[(size_t)NROWS * HDIM];
__device__ half_t g_Vth[(size_t)BATCH * HDIM * SEQ];
__device__ half_t g_Vtl[(size_t)BATCH * HDIM * SEQ];
__device__ __nv_bfloat16 g_Wh[3 * HDIM * EMBED];
__device__ __nv_bfloat16 g_Wl[3 * HDIM * EMBED];

// ---------------------------------------------------------------------------
__device__ __forceinline__ void mma_bf16(float* d, const uint32_t* a,
                                         uint32_t b0, uint32_t b1) {
    asm volatile(
        "mma.sync.aligned.m16n8k16.row.col.f32.bf16.bf16.f32 "
        "{%0,%1,%2,%3}, {%4,%5,%6,%7}, {%8,%9}, {%0,%1,%2,%3};"
        : "+f"(d[0]), "+f"(d[1]), "+f"(d[2]), "+f"(d[3])
        : "r"(a[0]), "r"(a[1]), "r"(a[2]), "r"(a[3]), "r"(b0), "r"(b1));
}

// pack 2 floats -> bf16x2 hi and lo words
__device__ __forceinline__ void split2(float x, float y, uint32_t& h, uint32_t& l) {
    const __nv_bfloat162 hh = __floats2bfloat162_rn(x, y);
    const __nv_bfloat162 ll = __floats2bfloat162_rn(
        x - __bfloat162float(hh.x), y - __bfloat162float(hh.y));
    h = *(const uint32_t*)&hh;
    l = *(const uint32_t*)&ll;
}

// ---------------------------------------------------------------------------
// W convert: [E,D] fp32 -> g_Wh/g_Wl [mat][n=d][k=e] split bf16 (transposed)
// ---------------------------------------------------------------------------
__global__ void wconv_kernel(const float* __restrict__ Wq,
                             const float* __restrict__ Wk,
                             const float* __restrict__ Wv)
{
    const int idx = blockIdx.x * 256 + threadIdx.x;   // 73728 total
    const int mat = idx / (HDIM * EMBED);
    const int rem = idx % (HDIM * EMBED);
    const int n = rem / EMBED;
    const int k = rem % EMBED;
    const float* W = (mat == 0) ? Wq : ((mat == 1) ? Wk : Wv);
    const float w = W[(size_t)k * HDIM + n];
    const __nv_bfloat16 hi = __float2bfloat16(w);
    const __nv_bfloat16 lo = __float2bfloat16(w - __bfloat162float(hi));
    g_Wh[idx] = hi;
    g_Wl[idx] = lo;
}

// ---------------------------------------------------------------------------
// Projection via HMMA: per CTA M=128, N=192 (Q|K|V), K=384 in 6 chunks of 64.
// 8 warps = 4(m) x 2(n); warp tile 32 x 96. acc += Ah*Bh + Ah*Bl + Al*Bh.
// Epilogue: stage fp32 in smem, emit split-bf16 Q/K [b][s][d] and V^T [b][d][s].
// ---------------------------------------------------------------------------
#define AK_LD 72
#define OFF_AH 0
#define OFF_AL (OFF_AH + 128 * AK_LD)
#define OFF_BH (OFF_AL + 128 * AK_LD)
#define OFF_BL (OFF_BH + 192 * AK_LD)
#define MMA_SMEM_HALVES (OFF_BL + 192 * AK_LD)   // 46080 halves = 92160 B
#define ST_LD 196
#define PJ_SMEM_BYTES (128 * ST_LD * 4 > MMA_SMEM_HALVES * 2 ? 128 * ST_LD * 4 : MMA_SMEM_HALVES * 2)

__global__ __launch_bounds__(256) void proj_kernel(const float* __restrict__ X)
{
    extern __shared__ char smraw[];
    half_t* Ah = (half_t*)(smraw) + OFF_AH;
    half_t* Al = (half_t*)(smraw) + OFF_AL;
    half_t* Bh = (half_t*)(smraw) + OFF_BH;
    half_t* Bl = (half_t*)(smraw) + OFF_BL;
    float*  stage = (float*)smraw;

    const int tid = threadIdx.x;
    const int lane = tid & 31;
    const int wid = tid >> 5;
    const int warp_m = wid & 3;
    const int warp_n = wid >> 2;
    const int row0 = blockIdx.x * 128;

    float acc[2][12][4];
#pragma unroll
    for (int mt = 0; mt < 2; ++mt)
#pragma unroll
        for (int nt = 0; nt < 12; ++nt)
#pragma unroll
            for (int i = 0; i < 4; ++i) acc[mt][nt][i] = 0.0f;

    const int r_fr = lane >> 2;
    const int c_fr = (lane & 3) * 2;

    for (int c = 0; c < 6; ++c) {
#pragma unroll
        for (int i = 0; i < 8; ++i) {
            const int idx = i * 256 + tid;
            const int m = idx >> 4;
            const int c4 = (idx & 15) * 4;
            const float4 v = *(const float4*)(X + (size_t)(row0 + m) * EMBED + c * 64 + c4);
            uint32_t h0, l0, h1, l1;
            split2(v.x, v.y, h0, l0);
            split2(v.z, v.w, h1, l1);
            uint2 hv, lv;
            hv.x = h0; hv.y = h1; lv.x = l0; lv.y = l1;
            *(uint2*)(Ah + m * AK_LD + c4) = hv;
            *(uint2*)(Al + m * AK_LD + c4) = lv;
        }
#pragma unroll
        for (int i = 0; i < 6; ++i) {
            const int idx = i * 256 + tid;
            const int n = idx >> 3;
            const int q = idx & 7;
            const size_t gb = (size_t)n * EMBED + c * 64 + q * 8;
            *(float4*)(Bh + n * AK_LD + q * 8) = *(const float4*)((const half_t*)g_Wh + gb);
            *(float4*)(Bl + n * AK_LD + q * 8) = *(const float4*)((const half_t*)g_Wl + gb);
        }
        __syncthreads();

#pragma unroll
        for (int ks = 0; ks < 4; ++ks) {
            const int kc = ks * 16 + c_fr;
            uint32_t ah[2][4], al[2][4];
#pragma unroll
            for (int mt = 0; mt < 2; ++mt) {
                const int mb = warp_m * 32 + mt * 16;
                ah[mt][0] = *(const uint32_t*)(Ah + (mb + r_fr) * AK_LD + kc);
                ah[mt][1] = *(const uint32_t*)(Ah + (mb + r_fr + 8) * AK_LD + kc);
                ah[mt][2] = *(const uint32_t*)(Ah + (mb + r_fr) * AK_LD + kc + 8);
                ah[mt][3] = *(const uint32_t*)(Ah + (mb + r_fr + 8) * AK_LD + kc + 8);
                al[mt][0] = *(const uint32_t*)(Al + (mb + r_fr) * AK_LD + kc);
                al[mt][1] = *(const uint32_t*)(Al + (mb + r_fr + 8) * AK_LD + kc);
                al[mt][2] = *(const uint32_t*)(Al + (mb + r_fr) * AK_LD + kc + 8);
                al[mt][3] = *(const uint32_t*)(Al + (mb + r_fr + 8) * AK_LD + kc + 8);
            }
#pragma unroll
            for (int nt = 0; nt < 12; ++nt) {
                const int nb = warp_n * 96 + nt * 8 + r_fr;
                const uint32_t bh0 = *(const uint32_t*)(Bh + nb * AK_LD + kc);
                const uint32_t bh1 = *(const uint32_t*)(Bh + nb * AK_LD + kc + 8);
                const uint32_t bl0 = *(const uint32_t*)(Bl + nb * AK_LD + kc);
                const uint32_t bl1 = *(const uint32_t*)(Bl + nb * AK_LD + kc + 8);
                mma_bf16(acc[0][nt], ah[0], bh0, bh1);
                mma_bf16(acc[1][nt], ah[1], bh0, bh1);
                mma_bf16(acc[0][nt], ah[0], bl0, bl1);
                mma_bf16(acc[1][nt], ah[1], bl0, bl1);
                mma_bf16(acc[0][nt], al[0], bh0, bh1);
                mma_bf16(acc[1][nt], al[1], bh0, bh1);
            }
        }
        __syncthreads();
    }

    // --- stage accumulators to smem: stage[m][fused_col] ---
#pragma unroll
    for (int mt = 0; mt < 2; ++mt) {
        const int r0 = warp_m * 32 + mt * 16 + r_fr;
#pragma unroll
        for (int nt = 0; nt < 12; ++nt) {
            const int col = warp_n * 96 + nt * 8 + c_fr;
            float2 v0, v1;
            v0.x = acc[mt][nt][0]; v0.y = acc[mt][nt][1];
            v1.x = acc[mt][nt][2]; v1.y = acc[mt][nt][3];
            *(float2*)(stage + r0 * ST_LD + col)       = v0;
            *(float2*)(stage + (r0 + 8) * ST_LD + col) = v1;
        }
    }
    __syncthreads();

    const int b = row0 >> 8;
    const int sbase = row0 & 255;

    // --- Q (cols 0..63) / K (cols 64..127): split bf16 [b][s][d] ---
    for (int idx = tid; idx < 2048; idx += 256) {
        const int m = idx >> 4;
        const int q = (idx & 15) * 4;
        const size_t go = (size_t)(row0 + m) * HDIM + q;
        {
            const float4 v = *(const float4*)(stage + m * ST_LD + q);
            uint32_t h0, l0, h1, l1;
            split2(v.x, v.y, h0, l0);
            split2(v.z, v.w, h1, l1);
            uint2 hv, lv; hv.x = h0; hv.y = h1; lv.x = l0; lv.y = l1;
            *(uint2*)(g_Qh + go) = hv;
            *(uint2*)(g_Ql + go) = lv;
        }
        {
            const float4 v = *(const float4*)(stage + m * ST_LD + 64 + q);
            uint32_t h0, l0, h1, l1;
            split2(v.x, v.y, h0, l0);
            split2(v.z, v.w, h1, l1);
            uint2 hv, lv; hv.x = h0; hv.y = h1; lv.x = l0; lv.y = l1;
            *(uint2*)(g_Kh + go) = hv;
            *(uint2*)(g_Kl + go) = lv;
        }
    }
    // --- V (cols 128..191): split bf16 transposed [b][d][s] ---
    // 64 dims x 128 seq rows, 4 seq per iteration -> 2048 iterations.
    for (int idx = tid; idx < 2048; idx += 256) {
        const int d = idx >> 5;                  // 0..63
        const int s0 = (idx & 31) * 4;           // 0..124
        float v0 = stage[(s0 + 0) * ST_LD + 128 + d];
        float v1 = stage[(s0 + 1) * ST_LD + 128 + d];
        float v2 = stage[(s0 + 2) * ST_LD + 128 + d];
        float v3 = stage[(s0 + 3) * ST_LD + 128 + d];
        uint32_t h0, l0, h1, l1;
        split2(v0, v1, h0, l0);
        split2(v2, v3, h1, l1);
        uint2 hv, lv; hv.x = h0; hv.y = h1; lv.x = l0; lv.y = l1;
        const size_t go = ((size_t)b * HDIM + d) * SEQ + sbase + s0;
        *(uint2*)(g_Vth + go) = hv;
        *(uint2*)(g_Vtl + go) = lv;
    }
}

// ---------------------------------------------------------------------------
// Attention via HMMA. One block per (batch, 64-query tile), 8 warps (4m x 2n).
// Phase 1: S = scale*Q K^T (split bf16, 3 passes) -> fp32 smem, causal fused.
// Phase 2: softmax -> P split bf16 (Ph/Pl), rinv.
// Phase 3: O = P V (3 passes), rinv folded in epilogue.
// ---------------------------------------------------------------------------
#define QT_LDH 72     // halves stride, Q and K/V tiles
#define S_LD   260    // floats
#define P_LDH  264    // halves

#define AOFF_QH 0
#define AOFF_QL (AOFF_QH + 64 * QT_LDH)
#define AOFF_TH (AOFF_QL + 64 * QT_LDH)
#define AOFF_TL (AOFF_TH + 64 * QT_LDH)
#define AOFF_S_B   ((AOFF_TL + 64 * QT_LDH) * 2)          // 36864 bytes
#define AOFF_PH_B  (AOFF_S_B + 64 * S_LD * 4)             // 103424
#define AOFF_PL_B  (AOFF_PH_B + 64 * P_LDH * 2)           // 137216
#define AOFF_RI_B  (AOFF_PL_B + 64 * P_LDH * 2)           // 171008
#define AT_SMEM_BYTES (AOFF_RI_B + 256)                    // 171264

__global__ __launch_bounds__(256) void attn_kernel(float* __restrict__ Out)
{
    extern __shared__ char smr[];
    half_t* Qh = (half_t*)smr + AOFF_QH;
    half_t* Ql = (half_t*)smr + AOFF_QL;
    half_t* Th = (half_t*)smr + AOFF_TH;
    half_t* Tl = (half_t*)smr + AOFF_TL;
    float*  S  = (float*)(smr + AOFF_S_B);
    half_t* Ph = (half_t*)(smr + AOFF_PH_B);
    half_t* Pl = (half_t*)(smr + AOFF_PL_B);
    float*  rinv = (float*)(smr + AOFF_RI_B);

    const int tid = threadIdx.x;
    const int lane = tid & 31;
    const int wid = tid >> 5;
    const int warp_m = wid & 3;
    const int warp_n = wid >> 2;
    const int r_fr = lane >> 2;
    const int c_fr = (lane & 3) * 2;

    const int qt = blockIdx.x;
    const int b  = blockIdx.y;
    const int kvlen = (qt + 1) * 64;
    const float scale = 0.125f;

    // --- load Q tile (64 x 64 halves, hi+lo) ---
    {
        const half_t* Qhg = g_Qh + (size_t)(b * SEQ + qt * 64) * HDIM;
        const half_t* Qlg = g_Ql + (size_t)(b * SEQ + qt * 64) * HDIM;
        for (int idx = tid; idx < 512; idx += 256) {
            const int r = idx >> 3;
            const int q8 = (idx & 7) * 8;
            *(float4*)(Qh + r * QT_LDH + q8) = *(const float4*)(Qhg + r * HDIM + q8);
            *(float4*)(Ql + r * QT_LDH + q8) = *(const float4*)(Qlg + r * HDIM + q8);
        }
    }

    // --- phase 1: per K-tile mma ---
    for (int jt = 0; jt <= qt; ++jt) {
        const half_t* Khg = g_Kh + (size_t)(b * SEQ + jt * 64) * HDIM;
        const half_t* Klg = g_Kl + (size_t)(b * SEQ + jt * 64) * HDIM;
        for (int idx = tid; idx < 512; idx += 256) {
            const int r = idx >> 3;
            const int q8 = (idx & 7) * 8;
            *(float4*)(Th + r * QT_LDH + q8) = *(const float4*)(Khg + r * HDIM + q8);
            *(float4*)(Tl + r * QT_LDH + q8) = *(const float4*)(Klg + r * HDIM + q8);
        }
        __syncthreads();

        float acc[4][4];
#pragma unroll
        for (int nt = 0; nt < 4; ++nt)
#pragma unroll
            for (int i = 0; i < 4; ++i) acc[nt][i] = 0.0f;

#pragma unroll
        for (int ks = 0; ks < 4; ++ks) {
            const int kc = ks * 16 + c_fr;
            const int mb = warp_m * 16;
            uint32_t ah[4], al[4];
            ah[0] = *(const uint32_t*)(Qh + (mb + r_fr) * QT_LDH + kc);
            ah[1] = *(const uint32_t*)(Qh + (mb + r_fr + 8) * QT_LDH + kc);
            ah[2] = *(const uint32_t*)(Qh + (mb + r_fr) * QT_LDH + kc + 8);
            ah[3] = *(const uint32_t*)(Qh + (mb + r_fr + 8) * QT_LDH + kc + 8);
            al[0] = *(const uint32_t*)(Ql + (mb + r_fr) * QT_LDH + kc);
            al[1] = *(const uint32_t*)(Ql + (mb + r_fr + 8) * QT_LDH + kc);
            al[2] = *(const uint32_t*)(Ql + (mb + r_fr) * QT_LDH + kc + 8);
            al[3] = *(const uint32_t*)(Ql + (mb + r_fr + 8) * QT_LDH + kc + 8);
#pragma unroll
            for (int nt = 0; nt < 4; ++nt) {
                const int nb = warp_n * 32 + nt * 8 + r_fr;
                const uint32_t bh0 = *(const uint32_t*)(Th + nb * QT_LDH + kc);
                const uint32_t bh1 = *(const uint32_t*)(Th + nb * QT_LDH + kc + 8);
                const uint32_t bl0 = *(const uint32_t*)(Tl + nb * QT_LDH + kc);
                const uint32_t bl1 = *(const uint32_t*)(Tl + nb * QT_LDH + kc + 8);
                mma_bf16(acc[nt], ah, bh0, bh1);
                mma_bf16(acc[nt], ah, bl0, bl1);
                mma_bf16(acc[nt], al, bh0, bh1);
            }
        }

        // write S with scale + causal mask
        const int row0g = qt * 64 + warp_m * 16 + r_fr;
        const int row1g = row0g + 8;
        const int i0 = warp_m * 16 + r_fr;
#pragma unroll
        for (int nt = 0; nt < 4; ++nt) {
            const int colg = jt * 64 + warp_n * 32 + nt * 8 + c_fr;
            S[i0 * S_LD + colg]           = (colg     <= row0g) ? acc[nt][0] * scale : -3.0e38f;
            S[i0 * S_LD + colg + 1]       = (colg + 1 <= row0g) ? acc[nt][1] * scale : -3.0e38f;
            S[(i0 + 8) * S_LD + colg]     = (colg     <= row1g) ? acc[nt][2] * scale : -3.0e38f;
            S[(i0 + 8) * S_LD + colg + 1] = (colg + 1 <= row1g) ? acc[nt][3] * scale : -3.0e38f;
        }
        __syncthreads();
    }

    // --- phase 2: softmax rows -> Ph/Pl, rinv ---
    {
        const int row = tid >> 2;
        const int c   = tid & 3;
        float m = -3.4e38f;
        for (int j = c; j < kvlen; j += 4)
            m = fmaxf(m, S[row * S_LD + j]);
        m = fmaxf(m, __shfl_xor_sync(0xffffffffu, m, 1));
        m = fmaxf(m, __shfl_xor_sync(0xffffffffu, m, 2));
        float ssum = 0.0f;
        for (int j = c; j < kvlen; j += 4) {
            const float p = __expf(S[row * S_LD + j] - m);
            ssum += p;
            const __nv_bfloat16 hi = __float2bfloat16(p);
            Ph[row * P_LDH + j] = *(const half_t*)&hi;
            const __nv_bfloat16 lo = __float2bfloat16(p - __bfloat162float(hi));
            Pl[row * P_LDH + j] = *(const half_t*)&lo;
        }
        ssum += __shfl_xor_sync(0xffffffffu, ssum, 1);
        ssum += __shfl_xor_sync(0xffffffffu, ssum, 2);
        if (c == 0) rinv[row] = 1.0f / ssum;
    }
    __syncthreads();

    // --- phase 3: O = P V ---
    float o[4][4];
#pragma unroll
    for (int nt = 0; nt < 4; ++nt)
#pragma unroll
        for (int i = 0; i < 4; ++i) o[nt][i] = 0.0f;

    for (int jt = 0; jt <= qt; ++jt) {
        const half_t* Vhg = g_Vth + (size_t)b * HDIM * SEQ + jt * 64;
        const half_t* Vlg = g_Vtl + (size_t)b * HDIM * SEQ + jt * 64;
        for (int idx = tid; idx < 512; idx += 256) {
            const int d = idx >> 3;
            const int s8 = (idx & 7) * 8;
            *(float4*)(Th + d * QT_LDH + s8) = *(const float4*)(Vhg + (size_t)d * SEQ + s8);
            *(float4*)(Tl + d * QT_LDH + s8) = *(const float4*)(Vlg + (size_t)d * SEQ + s8);
        }
        __syncthreads();

#pragma unroll
        for (int ks = 0; ks < 4; ++ks) {
            const int kg = jt * 64 + ks * 16 + c_fr;   // global j
            const int kl = ks * 16 + c_fr;              // local j in tile
            const int mb = warp_m * 16;
            uint32_t ah[4], al[4];
            ah[0] = *(const uint32_t*)(Ph + (mb + r_fr) * P_LDH + kg);
            ah[1] = *(const uint32_t*)(Ph + (mb + r_fr + 8) * P_LDH + kg);
            ah[2] = *(const uint32_t*)(Ph + (mb + r_fr) * P_LDH + kg + 8);
            ah[3] = *(const uint32_t*)(Ph + (mb + r_fr + 8) * P_LDH + kg + 8);
            al[0] = *(const uint32_t*)(Pl + (mb + r_fr) * P_LDH + kg);
            al[1] = *(const uint32_t*)(Pl + (mb + r_fr + 8) * P_LDH + kg);
            al[2] = *(const uint32_t*)(Pl + (mb + r_fr) * P_LDH + kg + 8);
            al[3] = *(const uint32_t*)(Pl + (mb + r_fr + 8) * P_LDH + kg + 8);
#pragma unroll
            for (int nt = 0; nt < 4; ++nt) {
                const int nb = warp_n * 32 + nt * 8 + r_fr;   // d
                const uint32_t bh0 = *(const uint32_t*)(Th + nb * QT_LDH + kl);
                const uint32_t bh1 = *(const uint32_t*)(Th + nb * QT_LDH + kl + 8);
                const uint32_t bl0 = *(const uint32_t*)(Tl + nb * QT_LDH + kl);
                const uint32_t bl1 = *(const uint32_t*)(Tl + nb * QT_LDH + kl + 8);
                mma_bf16(o[nt], ah, bh0, bh1);
                mma_bf16(o[nt], ah, bl0, bl1);
                mma_bf16(o[nt], al, bh0, bh1);
            }
        }
        __syncthreads();
    }

    // --- epilogue ---
    {
        const int i0 = warp_m * 16 + r_fr;
        const float inv0 = rinv[i0];
        const float inv1 = rinv[i0 + 8];
        float* Og = Out + (size_t)(b * SEQ + qt * 64) * HDIM;
#pragma unroll
        for (int nt = 0; nt < 4; ++nt) {
            const int col = warp_n * 32 + nt * 8 + c_fr;
            float2 v0, v1;
            v0.x = o[nt][0] * inv0; v0.y = o[nt][1] * inv0;
            v1.x = o[nt][2] * inv1; v1.y = o[nt][3] * inv1;
            *(float2*)(Og + (size_t)i0 * HDIM + col)       = v0;
            *(float2*)(Og + (size_t)(i0 + 8) * HDIM + col) = v1;
        }
    }
}

// ---------------------------------------------------------------------------
extern "C" void kernel_launch(void* const* d_in, const int* in_sizes, int n_in,
                              void* d_out, int out_size)
{
    const float* X  = (const float*)d_in[0];   // [512,256,384]
    const float* Wk = (const float*)d_in[1];   // [384,64]
    const float* Wq = (const float*)d_in[2];   // [384,64]
    const float* Wv = (const float*)d_in[3];   // [384,64]
    float* Out = (float*)d_out;                // [512,256,64]

    (void)in_sizes; (void)n_in; (void)out_size;

    cudaFuncSetAttribute(proj_kernel,
                         cudaFuncAttributeMaxDynamicSharedMemorySize, PJ_SMEM_BYTES);
    cudaFuncSetAttribute(attn_kernel,
                         cudaFuncAttributeMaxDynamicSharedMemorySize, AT_SMEM_BYTES);

    wconv_kernel<<<288, 256>>>(Wq, Wk, Wv);
    proj_kernel<<<NROWS / 128, 256, PJ_SMEM_BYTES>>>(X);

    dim3 grid(SEQ / 64, BATCH);
    attn_kernel<<<grid, 256, AT_SMEM_BYTES>>>(Out);
}

// round 7
// speedup vs baseline: 1.1247x; 1.1247x over previous
#include <cuda_runtime.h>
#include <cuda_bf16.h>
#include <cstdint>

#define BATCH 512
#define SEQ   256
#define EMBED 384
#define HDIM  64
#define NROWS (BATCH * SEQ)   // 131072

typedef uint16_t half_t;

// ---------------------------------------------------------------------------
// Global scratch: projected Q/K/V in split bf16.
//   Qh/Ql, Kh/Kl: [b][s][d]   (row.col mma layout for S = Q K^T)
//   Vth/Vtl:      [b][d][s]   (B operand layout for O = P V)
// W split-bf16: [mat][n][k].
// ---------------------------------------------------------------------------
__device__ half_t g_Qh[(size_t)NROWS * HDIM];
__device__ half_t g_Ql[(size_t)NROWS * HDIM];
__device__ half_t g_Kh[(size_t)NROWS * HDIM];
__device__ half_t g_Kl[(size_t)NROWS * HDIM];
__device__ half_t g_Vth[(size_t)BATCH * HDIM * SEQ];
__device__ half_t g_Vtl[(size_t)BATCH * HDIM * SEQ];
__device__ __nv_bfloat16 g_Wh[3 * HDIM * EMBED];
__device__ __nv_bfloat16 g_Wl[3 * HDIM * EMBED];

// ---------------------------------------------------------------------------
__device__ __forceinline__ void mma_bf16(float* d, const uint32_t* a,
                                         uint32_t b0, uint32_t b1) {
    asm volatile(
        "mma.sync.aligned.m16n8k16.row.col.f32.bf16.bf16.f32 "
        "{%0,%1,%2,%3}, {%4,%5,%6,%7}, {%8,%9}, {%0,%1,%2,%3};"
        : "+f"(d[0]), "+f"(d[1]), "+f"(d[2]), "+f"(d[3])
        : "r"(a[0]), "r"(a[1]), "r"(a[2]), "r"(a[3]), "r"(b0), "r"(b1));
}

__device__ __forceinline__ void split2(float x, float y, uint32_t& h, uint32_t& l) {
    const __nv_bfloat162 hh = __floats2bfloat162_rn(x, y);
    const __nv_bfloat162 ll = __floats2bfloat162_rn(
        x - __bfloat162float(hh.x), y - __bfloat162float(hh.y));
    h = *(const uint32_t*)&hh;
    l = *(const uint32_t*)&ll;
}

// ---------------------------------------------------------------------------
// W convert
// ---------------------------------------------------------------------------
__global__ void wconv_kernel(const float* __restrict__ Wq,
                             const float* __restrict__ Wk,
                             const float* __restrict__ Wv)
{
    const int idx = blockIdx.x * 256 + threadIdx.x;
    const int mat = idx / (HDIM * EMBED);
    const int rem = idx % (HDIM * EMBED);
    const int n = rem / EMBED;
    const int k = rem % EMBED;
    const float* W = (mat == 0) ? Wq : ((mat == 1) ? Wk : Wv);
    const float w = W[(size_t)k * HDIM + n];
    const __nv_bfloat16 hi = __float2bfloat16(w);
    const __nv_bfloat16 lo = __float2bfloat16(w - __bfloat162float(hi));
    g_Wh[idx] = hi;
    g_Wl[idx] = lo;
}

// ---------------------------------------------------------------------------
// Projection via HMMA (unchanged from R6 — measured ~205us, correct).
// ---------------------------------------------------------------------------
#define AK_LD 72
#define OFF_AH 0
#define OFF_AL (OFF_AH + 128 * AK_LD)
#define OFF_BH (OFF_AL + 128 * AK_LD)
#define OFF_BL (OFF_BH + 192 * AK_LD)
#define MMA_SMEM_HALVES (OFF_BL + 192 * AK_LD)
#define ST_LD 196
#define PJ_SMEM_BYTES (128 * ST_LD * 4 > MMA_SMEM_HALVES * 2 ? 128 * ST_LD * 4 : MMA_SMEM_HALVES * 2)

__global__ __launch_bounds__(256) void proj_kernel(const float* __restrict__ X)
{
    extern __shared__ char smraw[];
    half_t* Ah = (half_t*)(smraw) + OFF_AH;
    half_t* Al = (half_t*)(smraw) + OFF_AL;
    half_t* Bh = (half_t*)(smraw) + OFF_BH;
    half_t* Bl = (half_t*)(smraw) + OFF_BL;
    float*  stage = (float*)smraw;

    const int tid = threadIdx.x;
    const int lane = tid & 31;
    const int wid = tid >> 5;
    const int warp_m = wid & 3;
    const int warp_n = wid >> 2;
    const int row0 = blockIdx.x * 128;

    float acc[2][12][4];
#pragma unroll
    for (int mt = 0; mt < 2; ++mt)
#pragma unroll
        for (int nt = 0; nt < 12; ++nt)
#pragma unroll
            for (int i = 0; i < 4; ++i) acc[mt][nt][i] = 0.0f;

    const int r_fr = lane >> 2;
    const int c_fr = (lane & 3) * 2;

    for (int c = 0; c < 6; ++c) {
#pragma unroll
        for (int i = 0; i < 8; ++i) {
            const int idx = i * 256 + tid;
            const int m = idx >> 4;
            const int c4 = (idx & 15) * 4;
            const float4 v = *(const float4*)(X + (size_t)(row0 + m) * EMBED + c * 64 + c4);
            uint32_t h0, l0, h1, l1;
            split2(v.x, v.y, h0, l0);
            split2(v.z, v.w, h1, l1);
            uint2 hv, lv;
            hv.x = h0; hv.y = h1; lv.x = l0; lv.y = l1;
            *(uint2*)(Ah + m * AK_LD + c4) = hv;
            *(uint2*)(Al + m * AK_LD + c4) = lv;
        }
#pragma unroll
        for (int i = 0; i < 6; ++i) {
            const int idx = i * 256 + tid;
            const int n = idx >> 3;
            const int q = idx & 7;
            const size_t gb = (size_t)n * EMBED + c * 64 + q * 8;
            *(float4*)(Bh + n * AK_LD + q * 8) = *(const float4*)((const half_t*)g_Wh + gb);
            *(float4*)(Bl + n * AK_LD + q * 8) = *(const float4*)((const half_t*)g_Wl + gb);
        }
        __syncthreads();

#pragma unroll
        for (int ks = 0; ks < 4; ++ks) {
            const int kc = ks * 16 + c_fr;
            uint32_t ah[2][4], al[2][4];
#pragma unroll
            for (int mt = 0; mt < 2; ++mt) {
                const int mb = warp_m * 32 + mt * 16;
                ah[mt][0] = *(const uint32_t*)(Ah + (mb + r_fr) * AK_LD + kc);
                ah[mt][1] = *(const uint32_t*)(Ah + (mb + r_fr + 8) * AK_LD + kc);
                ah[mt][2] = *(const uint32_t*)(Ah + (mb + r_fr) * AK_LD + kc + 8);
                ah[mt][3] = *(const uint32_t*)(Ah + (mb + r_fr + 8) * AK_LD + kc + 8);
                al[mt][0] = *(const uint32_t*)(Al + (mb + r_fr) * AK_LD + kc);
                al[mt][1] = *(const uint32_t*)(Al + (mb + r_fr + 8) * AK_LD + kc);
                al[mt][2] = *(const uint32_t*)(Al + (mb + r_fr) * AK_LD + kc + 8);
                al[mt][3] = *(const uint32_t*)(Al + (mb + r_fr + 8) * AK_LD + kc + 8);
            }
#pragma unroll
            for (int nt = 0; nt < 12; ++nt) {
                const int nb = warp_n * 96 + nt * 8 + r_fr;
                const uint32_t bh0 = *(const uint32_t*)(Bh + nb * AK_LD + kc);
                const uint32_t bh1 = *(const uint32_t*)(Bh + nb * AK_LD + kc + 8);
                const uint32_t bl0 = *(const uint32_t*)(Bl + nb * AK_LD + kc);
                const uint32_t bl1 = *(const uint32_t*)(Bl + nb * AK_LD + kc + 8);
                mma_bf16(acc[0][nt], ah[0], bh0, bh1);
                mma_bf16(acc[1][nt], ah[1], bh0, bh1);
                mma_bf16(acc[0][nt], ah[0], bl0, bl1);
                mma_bf16(acc[1][nt], ah[1], bl0, bl1);
                mma_bf16(acc[0][nt], al[0], bh0, bh1);
                mma_bf16(acc[1][nt], al[1], bh0, bh1);
            }
        }
        __syncthreads();
    }

#pragma unroll
    for (int mt = 0; mt < 2; ++mt) {
        const int r0 = warp_m * 32 + mt * 16 + r_fr;
#pragma unroll
        for (int nt = 0; nt < 12; ++nt) {
            const int col = warp_n * 96 + nt * 8 + c_fr;
            float2 v0, v1;
            v0.x = acc[mt][nt][0]; v0.y = acc[mt][nt][1];
            v1.x = acc[mt][nt][2]; v1.y = acc[mt][nt][3];
            *(float2*)(stage + r0 * ST_LD + col)       = v0;
            *(float2*)(stage + (r0 + 8) * ST_LD + col) = v1;
        }
    }
    __syncthreads();

    const int b = row0 >> 8;
    const int sbase = row0 & 255;

    for (int idx = tid; idx < 2048; idx += 256) {
        const int m = idx >> 4;
        const int q = (idx & 15) * 4;
        const size_t go = (size_t)(row0 + m) * HDIM + q;
        {
            const float4 v = *(const float4*)(stage + m * ST_LD + q);
            uint32_t h0, l0, h1, l1;
            split2(v.x, v.y, h0, l0);
            split2(v.z, v.w, h1, l1);
            uint2 hv, lv; hv.x = h0; hv.y = h1; lv.x = l0; lv.y = l1;
            *(uint2*)(g_Qh + go) = hv;
            *(uint2*)(g_Ql + go) = lv;
        }
        {
            const float4 v = *(const float4*)(stage + m * ST_LD + 64 + q);
            uint32_t h0, l0, h1, l1;
            split2(v.x, v.y, h0, l0);
            split2(v.z, v.w, h1, l1);
            uint2 hv, lv; hv.x = h0; hv.y = h1; lv.x = l0; lv.y = l1;
            *(uint2*)(g_Kh + go) = hv;
            *(uint2*)(g_Kl + go) = lv;
        }
    }
    for (int idx = tid; idx < 2048; idx += 256) {
        const int d = idx >> 5;
        const int s0 = (idx & 31) * 4;
        float v0 = stage[(s0 + 0) * ST_LD + 128 + d];
        float v1 = stage[(s0 + 1) * ST_LD + 128 + d];
        float v2 = stage[(s0 + 2) * ST_LD + 128 + d];
        float v3 = stage[(s0 + 3) * ST_LD + 128 + d];
        uint32_t h0, l0, h1, l1;
        split2(v0, v1, h0, l0);
        split2(v2, v3, h1, l1);
        uint2 hv, lv; hv.x = h0; hv.y = h1; lv.x = l0; lv.y = l1;
        const size_t go = ((size_t)b * HDIM + d) * SEQ + sbase + s0;
        *(uint2*)(g_Vth + go) = hv;
        *(uint2*)(g_Vtl + go) = lv;
    }
}

// ---------------------------------------------------------------------------
// FlashAttention-2 style attention. Grid (2, 512): 128 query rows per CTA.
// 8 warps, warp w owns rows w*16..w*16+15 (full rows -> quad-shfl softmax).
// Per 64-key tile: S in regs (C-frag), online softmax in regs, P converted
// to A-frags in regs (C-layout == A-layout identity), O += P·V. K/V tiles
// double-buffered in smem. Causal skip per warp.
// ---------------------------------------------------------------------------
#define FT_LD 72
#define BUF_HALVES (4 * 64 * FT_LD)           // Kh,Kl,Vh,Vl = 18432 halves
#define AT_SMEM_BYTES (2 * BUF_HALVES * 2)    // 73728 bytes

__global__ __launch_bounds__(256) void attn_kernel(float* __restrict__ Out)
{
    extern __shared__ char smr[];
    half_t* const buf[2] = { (half_t*)smr, (half_t*)smr + BUF_HALVES };

    const int tid = threadIdx.x;
    const int lane = tid & 31;
    const int wid = tid >> 5;
    const int r_fr = lane >> 2;
    const int c_fr = (lane & 3) * 2;
    const int mb = wid * 16;

    const int qt = blockIdx.x;          // 0..1 (128-row q tiles)
    const int b  = blockIdx.y;
    const int q0 = qt * 128;
    const int njt = qt * 2 + 2;         // causal tile count
    const float scale = 0.125f;

    // --- stage Q (hi+lo) into buf1, extract A-fragments, release smem ---
    uint32_t qh[4][4], ql[4][4];
    {
        half_t* Qsh = buf[1];
        half_t* Qsl = buf[1] + 128 * FT_LD;
        const half_t* Qhg = g_Qh + (size_t)(b * SEQ + q0) * HDIM;
        const half_t* Qlg = g_Ql + (size_t)(b * SEQ + q0) * HDIM;
        for (int idx = tid; idx < 1024; idx += 256) {
            const int r = idx >> 3;
            const int q8 = (idx & 7) * 8;
            *(float4*)(Qsh + r * FT_LD + q8) = *(const float4*)(Qhg + r * HDIM + q8);
            *(float4*)(Qsl + r * FT_LD + q8) = *(const float4*)(Qlg + r * HDIM + q8);
        }
        __syncthreads();
#pragma unroll
        for (int ks = 0; ks < 4; ++ks) {
            const int kc = ks * 16 + c_fr;
            qh[ks][0] = *(const uint32_t*)(Qsh + (mb + r_fr) * FT_LD + kc);
            qh[ks][1] = *(const uint32_t*)(Qsh + (mb + r_fr + 8) * FT_LD + kc);
            qh[ks][2] = *(const uint32_t*)(Qsh + (mb + r_fr) * FT_LD + kc + 8);
            qh[ks][3] = *(const uint32_t*)(Qsh + (mb + r_fr + 8) * FT_LD + kc + 8);
            ql[ks][0] = *(const uint32_t*)(Qsl + (mb + r_fr) * FT_LD + kc);
            ql[ks][1] = *(const uint32_t*)(Qsl + (mb + r_fr + 8) * FT_LD + kc);
            ql[ks][2] = *(const uint32_t*)(Qsl + (mb + r_fr) * FT_LD + kc + 8);
            ql[ks][3] = *(const uint32_t*)(Qsl + (mb + r_fr + 8) * FT_LD + kc + 8);
        }
        __syncthreads();
    }

    // --- running state ---
    float o[8][4];
#pragma unroll
    for (int nt = 0; nt < 8; ++nt)
#pragma unroll
        for (int i = 0; i < 4; ++i) o[nt][i] = 0.0f;
    float m0 = -3.4e38f, m1 = -3.4e38f, l0 = 0.0f, l1 = 0.0f;

    const half_t* Khg = g_Kh + (size_t)b * SEQ * HDIM;
    const half_t* Klg = g_Kl + (size_t)b * SEQ * HDIM;
    const half_t* Vhg = g_Vth + (size_t)b * HDIM * SEQ;
    const half_t* Vlg = g_Vtl + (size_t)b * HDIM * SEQ;

    // tile loader: 64 keys (hi+lo) + 64 dims of V^T (hi+lo)
    auto load_tile = [&](int jt, half_t* dst) {
        half_t* Kh = dst;
        half_t* Kl = dst + 64 * FT_LD;
        half_t* Vh = dst + 2 * 64 * FT_LD;
        half_t* Vl = dst + 3 * 64 * FT_LD;
        const half_t* kh = Khg + (size_t)jt * 64 * HDIM;
        const half_t* kl = Klg + (size_t)jt * 64 * HDIM;
        const half_t* vh = Vhg + jt * 64;
        const half_t* vl = Vlg + jt * 64;
        for (int idx = tid; idx < 512; idx += 256) {
            const int r = idx >> 3;
            const int q8 = (idx & 7) * 8;
            *(float4*)(Kh + r * FT_LD + q8) = *(const float4*)(kh + r * HDIM + q8);
            *(float4*)(Kl + r * FT_LD + q8) = *(const float4*)(kl + r * HDIM + q8);
            *(float4*)(Vh + r * FT_LD + q8) = *(const float4*)(vh + (size_t)r * SEQ + q8);
            *(float4*)(Vl + r * FT_LD + q8) = *(const float4*)(vl + (size_t)r * SEQ + q8);
        }
    };

    load_tile(0, buf[0]);
    __syncthreads();

    for (int jt = 0; jt < njt; ++jt) {
        half_t* cur = buf[jt & 1];
        if (jt + 1 < njt) load_tile(jt + 1, buf[(jt + 1) & 1]);

        // warp-uniform causal skip: whole tile masked for this warp's rows?
        const bool active = (jt * 64) <= (q0 + mb + 15);
        if (active) {
            half_t* Kh = cur;
            half_t* Kl = cur + 64 * FT_LD;
            half_t* Vh = cur + 2 * 64 * FT_LD;
            half_t* Vl = cur + 3 * 64 * FT_LD;

            // --- S = Q K^T (3 split passes) ---
            float s[8][4];
#pragma unroll
            for (int nt = 0; nt < 8; ++nt)
#pragma unroll
                for (int i = 0; i < 4; ++i) s[nt][i] = 0.0f;
#pragma unroll
            for (int ks = 0; ks < 4; ++ks) {
                const int kc = ks * 16 + c_fr;
#pragma unroll
                for (int nt = 0; nt < 8; ++nt) {
                    const half_t* kb = Kh + (nt * 8 + r_fr) * FT_LD + kc;
                    const half_t* kbl = Kl + (nt * 8 + r_fr) * FT_LD + kc;
                    const uint32_t bh0 = *(const uint32_t*)kb;
                    const uint32_t bh1 = *(const uint32_t*)(kb + 8);
                    const uint32_t bl0 = *(const uint32_t*)kbl;
                    const uint32_t bl1 = *(const uint32_t*)(kbl + 8);
                    mma_bf16(s[nt], qh[ks], bh0, bh1);
                    mma_bf16(s[nt], qh[ks], bl0, bl1);
                    mma_bf16(s[nt], ql[ks], bh0, bh1);
                }
            }

            // --- scale + causal mask ---
            const int rowg0 = q0 + mb + r_fr;
            const int rowg1 = rowg0 + 8;
            const bool needm = (jt * 64 + 63) > (q0 + mb);
#pragma unroll
            for (int nt = 0; nt < 8; ++nt) {
                const int colg = jt * 64 + nt * 8 + c_fr;
                s[nt][0] *= scale; s[nt][1] *= scale;
                s[nt][2] *= scale; s[nt][3] *= scale;
                if (needm) {
                    if (colg     > rowg0) s[nt][0] = -3.4e38f;
                    if (colg + 1 > rowg0) s[nt][1] = -3.4e38f;
                    if (colg     > rowg1) s[nt][2] = -3.4e38f;
                    if (colg + 1 > rowg1) s[nt][3] = -3.4e38f;
                }
            }

            // --- online softmax: row max (quad shfl) ---
            float mx0 = -3.4e38f, mx1 = -3.4e38f;
#pragma unroll
            for (int nt = 0; nt < 8; ++nt) {
                mx0 = fmaxf(mx0, fmaxf(s[nt][0], s[nt][1]));
                mx1 = fmaxf(mx1, fmaxf(s[nt][2], s[nt][3]));
            }
            mx0 = fmaxf(mx0, __shfl_xor_sync(0xffffffffu, mx0, 1));
            mx0 = fmaxf(mx0, __shfl_xor_sync(0xffffffffu, mx0, 2));
            mx1 = fmaxf(mx1, __shfl_xor_sync(0xffffffffu, mx1, 1));
            mx1 = fmaxf(mx1, __shfl_xor_sync(0xffffffffu, mx1, 2));
            const float mn0 = fmaxf(m0, mx0);
            const float mn1 = fmaxf(m1, mx1);
            const float a0 = __expf(m0 - mn0);
            const float a1 = __expf(m1 - mn1);
            l0 *= a0; l1 *= a1;
#pragma unroll
            for (int nt = 0; nt < 8; ++nt) {
                o[nt][0] *= a0; o[nt][1] *= a0;
                o[nt][2] *= a1; o[nt][3] *= a1;
            }
            m0 = mn0; m1 = mn1;

            // --- P = exp(S-m), split to bf16 A-frags in regs ---
            uint32_t pa[4][4], pl[4][4];
            float sum0 = 0.0f, sum1 = 0.0f;
#pragma unroll
            for (int nt = 0; nt < 8; ++nt) {
                const float p0 = __expf(s[nt][0] - mn0);
                const float p1 = __expf(s[nt][1] - mn0);
                const float p2 = __expf(s[nt][2] - mn1);
                const float p3 = __expf(s[nt][3] - mn1);
                sum0 += p0 + p1;
                sum1 += p2 + p3;
                uint32_t h01, l01, h23, l23;
                split2(p0, p1, h01, l01);
                split2(p2, p3, h23, l23);
                const int ks = nt >> 1;
                const int off = (nt & 1) * 2;
                pa[ks][off]     = h01;  // (row r_fr,   k chunk)
                pa[ks][off + 1] = h23;  // (row r_fr+8, k chunk)
                pl[ks][off]     = l01;
                pl[ks][off + 1] = l23;
            }
            sum0 += __shfl_xor_sync(0xffffffffu, sum0, 1);
            sum0 += __shfl_xor_sync(0xffffffffu, sum0, 2);
            sum1 += __shfl_xor_sync(0xffffffffu, sum1, 1);
            sum1 += __shfl_xor_sync(0xffffffffu, sum1, 2);
            l0 += sum0; l1 += sum1;

            // NOTE: pa layout: a0=(r,kc),a1=(r+8,kc),a2=(r,kc+8),a3=(r+8,kc+8)
            // pa[ks][off] with off=0 covers cols ks*16+c_fr (nt even),
            // off=2 covers ks*16+8+c_fr (nt odd) -> reorder to frag order:
            uint32_t paf[4][4], plf[4][4];
#pragma unroll
            for (int ks = 0; ks < 4; ++ks) {
                paf[ks][0] = pa[ks][0]; paf[ks][1] = pa[ks][1];
                paf[ks][2] = pa[ks][2]; paf[ks][3] = pa[ks][3];
                plf[ks][0] = pl[ks][0]; plf[ks][1] = pl[ks][1];
                plf[ks][2] = pl[ks][2]; plf[ks][3] = pl[ks][3];
            }

            // --- O += P V (3 split passes) ---
#pragma unroll
            for (int ks = 0; ks < 4; ++ks) {
                const int kc = ks * 16 + c_fr;
#pragma unroll
                for (int nto = 0; nto < 8; ++nto) {
                    const half_t* vb = Vh + (nto * 8 + r_fr) * FT_LD + kc;
                    const half_t* vbl = Vl + (nto * 8 + r_fr) * FT_LD + kc;
                    const uint32_t bh0 = *(const uint32_t*)vb;
                    const uint32_t bh1 = *(const uint32_t*)(vb + 8);
                    const uint32_t bl0 = *(const uint32_t*)vbl;
                    const uint32_t bl1 = *(const uint32_t*)(vbl + 8);
                    mma_bf16(o[nto], paf[ks], bh0, bh1);
                    mma_bf16(o[nto], paf[ks], bl0, bl1);
                    mma_bf16(o[nto], plf[ks], bh0, bh1);
                }
            }
        }
        __syncthreads();   // next-tile loads complete; cur free for reuse
    }

    // --- epilogue: O / l ---
    {
        const float r0v = 1.0f / l0;
        const float r1v = 1.0f / l1;
        float* Og = Out + (size_t)(b * SEQ + q0 + mb) * HDIM;
#pragma unroll
        for (int nto = 0; nto < 8; ++nto) {
            const int col = nto * 8 + c_fr;
            float2 v0, v1;
            v0.x = o[nto][0] * r0v; v0.y = o[nto][1] * r0v;
            v1.x = o[nto][2] * r1v; v1.y = o[nto][3] * r1v;
            *(float2*)(Og + (size_t)r_fr * HDIM + col)       = v0;
            *(float2*)(Og + (size_t)(r_fr + 8) * HDIM + col) = v1;
        }
    }
}

// ---------------------------------------------------------------------------
extern "C" void kernel_launch(void* const* d_in, const int* in_sizes, int n_in,
                              void* d_out, int out_size)
{
    const float* X  = (const float*)d_in[0];   // [512,256,384]
    const float* Wk = (const float*)d_in[1];   // [384,64]
    const float* Wq = (const float*)d_in[2];   // [384,64]
    const float* Wv = (const float*)d_in[3];   // [384,64]
    float* Out = (float*)d_out;                // [512,256,64]

    (void)in_sizes; (void)n_in; (void)out_size;

    cudaFuncSetAttribute(proj_kernel,
                         cudaFuncAttributeMaxDynamicSharedMemorySize, PJ_SMEM_BYTES);
    cudaFuncSetAttribute(attn_kernel,
                         cudaFuncAttributeMaxDynamicSharedMemorySize, AT_SMEM_BYTES);

    wconv_kernel<<<288, 256>>>(Wq, Wk, Wv);
    proj_kernel<<<NROWS / 128, 256, PJ_SMEM_BYTES>>>(X);

    dim3 grid(2, BATCH);
    attn_kernel<<<grid, 256, AT_SMEM_BYTES>>>(Out);
}